// round 1
// baseline (speedup 1.0000x reference)
#include <cuda_runtime.h>
#include <stdint.h>

#define P1 2654435761u
#define P2 805459861u

template <bool POW2>
__global__ __launch_bounds__(256)
void hash_interp_kernel(const float* __restrict__ pts,
                        const float* __restrict__ feat,
                        float* __restrict__ out,
                        int n, unsigned buckets, unsigned mask)
{
    int i = blockIdx.x * blockDim.x + threadIdx.x;
    if (i >= n) return;

    // point coords
    float px = pts[3 * i + 0];
    float py = pts[3 * i + 1];
    float pz = pts[3 * i + 2];

    // continuous grid coords: match reference's pts / 0.005f exactly
    float qx = px / 0.005f;
    float qy = py / 0.005f;
    float qz = pz / 0.005f;

    float bxf = floorf(qx);
    float byf = floorf(qy);
    float bzf = floorf(qz);
    int bx = (int)bxf, by = (int)byf, bz = (int)bzf;

    float fx = qx - bxf;
    float fy = qy - byf;
    float fz = qz - bzf;

    // per-axis hash terms for corner 0 and corner 1
    unsigned hx0 = (unsigned)bx;            // * 1
    unsigned hx1 = (unsigned)(bx + 1);
    unsigned hy0 = (unsigned)by * P1;
    unsigned hy1 = hy0 + P1;
    unsigned hz0 = (unsigned)bz * P2;
    unsigned hz1 = hz0 + P2;

    unsigned slot[8];
    // x-fastest corner order: (0,0,0),(1,0,0),(0,1,0),(1,1,0),(0,0,1),(1,0,1),(0,1,1),(1,1,1)
    unsigned h0 = hx0 ^ hy0 ^ hz0;
    unsigned h1 = hx1 ^ hy0 ^ hz0;
    unsigned h2 = hx0 ^ hy1 ^ hz0;
    unsigned h3 = hx1 ^ hy1 ^ hz0;
    unsigned h4 = hx0 ^ hy0 ^ hz1;
    unsigned h5 = hx1 ^ hy0 ^ hz1;
    unsigned h6 = hx0 ^ hy1 ^ hz1;
    unsigned h7 = hx1 ^ hy1 ^ hz1;
    if (POW2) {
        slot[0] = h0 & mask; slot[1] = h1 & mask; slot[2] = h2 & mask; slot[3] = h3 & mask;
        slot[4] = h4 & mask; slot[5] = h5 & mask; slot[6] = h6 & mask; slot[7] = h7 & mask;
    } else {
        slot[0] = h0 % buckets; slot[1] = h1 % buckets; slot[2] = h2 % buckets; slot[3] = h3 % buckets;
        slot[4] = h4 % buckets; slot[5] = h5 % buckets; slot[6] = h6 % buckets; slot[7] = h7 % buckets;
    }

    // trilinear weights, corner order as above
    float wx0 = 1.0f - fx, wx1 = fx;
    float wy0 = 1.0f - fy, wy1 = fy;
    float wz0 = 1.0f - fz, wz1 = fz;
    float w[8];
    w[0] = wx0 * wy0 * wz0;
    w[1] = wx1 * wy0 * wz0;
    w[2] = wx0 * wy1 * wz0;
    w[3] = wx1 * wy1 * wz0;
    w[4] = wx0 * wy0 * wz1;
    w[5] = wx1 * wy0 * wz1;
    w[6] = wx0 * wy1 * wz1;
    w[7] = wx1 * wy1 * wz1;

    // issue all 16 vector gathers up-front for max MLP
    float4 lo[8], hi[8];
#pragma unroll
    for (int c = 0; c < 8; c++) {
        const float4* fp = reinterpret_cast<const float4*>(feat + (size_t)slot[c] * 8);
        lo[c] = __ldg(fp + 0);
        hi[c] = __ldg(fp + 1);
    }

    float a0 = 0.f, a1 = 0.f, a2 = 0.f, a3 = 0.f;
    float a4 = 0.f, a5 = 0.f, a6 = 0.f, a7 = 0.f;
#pragma unroll
    for (int c = 0; c < 8; c++) {
        float wc = w[c];
        a0 = fmaf(wc, lo[c].x, a0);
        a1 = fmaf(wc, lo[c].y, a1);
        a2 = fmaf(wc, lo[c].z, a2);
        a3 = fmaf(wc, lo[c].w, a3);
        a4 = fmaf(wc, hi[c].x, a4);
        a5 = fmaf(wc, hi[c].y, a5);
        a6 = fmaf(wc, hi[c].z, a6);
        a7 = fmaf(wc, hi[c].w, a7);
    }

    float4* op = reinterpret_cast<float4*>(out + (size_t)i * 8);
    op[0] = make_float4(a0, a1, a2, a3);
    op[1] = make_float4(a4, a5, a6, a7);
}

extern "C" void kernel_launch(void* const* d_in, const int* in_sizes, int n_in,
                              void* d_out, int out_size)
{
    const float* pts  = (const float*)d_in[0];
    const float* feat = (const float*)d_in[1];
    float* out = (float*)d_out;

    int n = in_sizes[0] / 3;
    unsigned buckets = (unsigned)(in_sizes[1] / 8);
    unsigned mask = buckets - 1u;
    bool pow2 = (buckets & (buckets - 1u)) == 0u;

    int threads = 256;
    int blocks = (n + threads - 1) / threads;
    if (pow2) {
        hash_interp_kernel<true><<<blocks, threads>>>(pts, feat, out, n, buckets, mask);
    } else {
        hash_interp_kernel<false><<<blocks, threads>>>(pts, feat, out, n, buckets, mask);
    }
}